// round 14
// baseline (speedup 1.0000x reference)
#include <cuda_runtime.h>
#include <cstdint>

#define N_ENT 50000
#define R_REL 16
#define D_EMB 64
#define F_IN  128
#define E_EDGE 100000
#define NEDGE (R_REL * E_EDGE)          // 1.6M
#define NTILE 391                        // ceil(N_ENT/128)
#define NB (R_REL * NTILE)               // 6256 buckets (r, col-tile)
#define NL 2

// ---------------- scratch (device globals; allocation-free rule) ------------
__device__ float g_emb[(size_t)N_ENT * D_EMB];                 // 12.8 MB
__device__ float g_acc1[(size_t)N_ENT * D_EMB];                // 12.8 MB (L2-hot)
__device__ float g_acc2[(size_t)N_ENT * D_EMB];                // 12.8 MB (L2-hot)
__device__ int   g_bcnt[NB];
__device__ int   g_bstart[NB + 1];
__device__ int   g_bcur[NB];
__device__ int2  g_recs[NEDGE];          // {(dest_row<<7)|col_local, val bits}

#define CVT_BF16X2(res, a, b) \
    asm("cvt.rn.satfinite.bf16x2.f32 %0, %1, %2;" : "=r"(res) : "f"(b), "f"(a))

__device__ __forceinline__ void split_pair(float2 f, uint32_t& h, uint32_t& l) {
    CVT_BF16X2(h, f.x, f.y);
    float h0 = __uint_as_float(h << 16);
    float h1 = __uint_as_float(h & 0xFFFF0000u);
    CVT_BF16X2(l, f.x - h0, f.y - h1);
}

#define MMA_BF16(c, a, b0, b1) \
    asm volatile("mma.sync.aligned.m16n8k16.row.col.f32.bf16.bf16.f32 " \
        "{%0,%1,%2,%3}, {%4,%5,%6,%7}, {%8,%9}, {%0,%1,%2,%3};" \
        : "+f"((c)[0]), "+f"((c)[1]), "+f"((c)[2]), "+f"((c)[3]) \
        : "r"((a)[0]), "r"((a)[1]), "r"((a)[2]), "r"((a)[3]), \
          "r"(b0), "r"(b1))

#define AW 36
#define BW 68

// ---------------------------------------------------------------------------
// Input GEMM via HMMA (proven) + epilogue zeroes bucket counters
// ---------------------------------------------------------------------------
#define IN_SM_AH 0
#define IN_SM_AL (128 * AW)
#define IN_SM_BH (2 * 128 * AW)
#define IN_SM_BL (2 * 128 * AW + 32 * BW)
#define IN_SM_WORDS (2 * 128 * AW + 2 * 32 * BW)   // 13568 words

__global__ void __launch_bounds__(256)
k_input_hmma(const float* __restrict__ x,
             const float* __restrict__ ent_emb,
             int nrows) {
    extern __shared__ uint32_t sw[];
    uint32_t* sAh = sw + IN_SM_AH;
    uint32_t* sAl = sw + IN_SM_AL;
    uint32_t* sBh = sw + IN_SM_BH;
    uint32_t* sBl = sw + IN_SM_BL;

    const int tid  = threadIdx.x;
    const int base = blockIdx.x * 128;

    const int warp = tid >> 5;
    const int lane = tid & 31;
    const int g = lane >> 2;
    const int t = lane & 3;
    const int wrow = warp * 16;

    float acc[8][4];
#pragma unroll
    for (int j = 0; j < 8; j++)
#pragma unroll
        for (int q = 0; q < 4; q++) acc[j][q] = 0.f;

    for (int h = 0; h < 2; h++) {
        __syncthreads();
#pragma unroll
        for (int i = 0; i < 16; i++) {
            int p   = tid + i * 256;
            int row = p >> 5;
            int e2  = p & 31;
            float2 f = make_float2(0.f, 0.f);
            if (base + row < nrows)
                f = *reinterpret_cast<const float2*>(
                    x + (size_t)(base + row) * F_IN + h * 64 + e2 * 2);
            uint32_t hh, ll; split_pair(f, hh, ll);
            sAh[row * AW + e2] = hh;
            sAl[row * AW + e2] = ll;
        }
#pragma unroll
        for (int i = 0; i < 8; i++) {
            int p  = tid + i * 256;
            int d  = p >> 5;
            int e2 = p & 31;
            int k  = h * 64 + e2 * 2;
            float2 f = make_float2(ent_emb[(size_t)k * D_EMB + d],
                                   ent_emb[(size_t)(k + 1) * D_EMB + d]);
            uint32_t hh, ll; split_pair(f, hh, ll);
            sBh[e2 * BW + d] = hh;
            sBl[e2 * BW + d] = ll;
        }
        __syncthreads();

#pragma unroll
        for (int ks = 0; ks < 4; ks++) {
            const int r0 = (wrow + g) * AW;
            const int r1 = (wrow + g + 8) * AW;
            const int eb = ks * 8 + t;
            uint32_t ah[4], al[4];
            ah[0] = sAh[r0 + eb];     ah[1] = sAh[r1 + eb];
            ah[2] = sAh[r0 + eb + 4]; ah[3] = sAh[r1 + eb + 4];
            al[0] = sAl[r0 + eb];     al[1] = sAl[r1 + eb];
            al[2] = sAl[r0 + eb + 4]; al[3] = sAl[r1 + eb + 4];

            const int kb0 = (ks * 8 + t) * BW;
            const int kb1 = (ks * 8 + t + 4) * BW;
#pragma unroll
            for (int j = 0; j < 8; j++) {
                int n = j * 8 + g;
                uint32_t bh0 = sBh[kb0 + n], bh1 = sBh[kb1 + n];
                uint32_t bl0 = sBl[kb0 + n], bl1 = sBl[kb1 + n];
                MMA_BF16(acc[j], ah, bh0, bh1);
                MMA_BF16(acc[j], ah, bl0, bl1);
                MMA_BF16(acc[j], al, bh0, bh1);
            }
        }
    }

    {
        int row0 = base + wrow + g;
        int row1 = row0 + 8;
#pragma unroll
        for (int j = 0; j < 8; j++) {
            int col = j * 8 + t * 2;
            if (row0 < nrows)
                *reinterpret_cast<float2*>(g_emb + (size_t)row0 * D_EMB + col) =
                    make_float2(acc[j][0], acc[j][1]);
            if (row1 < nrows)
                *reinterpret_cast<float2*>(g_emb + (size_t)row1 * D_EMB + col) =
                    make_float2(acc[j][2], acc[j][3]);
        }
    }

    // epilogue: zero bucket counters (25KB total across the grid)
    {
        int gt = blockIdx.x * 256 + tid;
        int stride = gridDim.x * 256;
        for (int i = gt; i < NB; i += stride) g_bcnt[i] = 0;
    }
}

// ---------------------------------------------------------------------------
// Bucket build: bucket = r*NTILE + (col>>7)  (fused kernel consumes segments
// at exactly this granularity; intra-bucket order is irrelevant)
// ---------------------------------------------------------------------------
__global__ void k_hist(const int* __restrict__ ecol) {
    int i = blockIdx.x * blockDim.x + threadIdx.x;
    if (i >= NEDGE) return;
    int r = i / E_EDGE;
    atomicAdd(&g_bcnt[r * NTILE + (__ldg(ecol + i) >> 7)], 1);
}

// single-CTA exclusive scan over 6256 buckets
__global__ void k_bscan() {
    __shared__ int ss[1024];
    const int t = threadIdx.x;
    const int PER = (NB + 1023) / 1024;       // 7
    int loc[PER];
    int s = 0;
#pragma unroll
    for (int k = 0; k < PER; k++) {
        int i = t * PER + k;
        int v = (i < NB) ? g_bcnt[i] : 0;
        loc[k] = s;                            // local exclusive
        s += v;
    }
    ss[t] = s;
    __syncthreads();
    for (int off = 1; off < 1024; off <<= 1) {
        int v = (t >= off) ? ss[t - off] : 0;
        __syncthreads();
        ss[t] += v;
        __syncthreads();
    }
    int excl = ss[t] - s;
#pragma unroll
    for (int k = 0; k < PER; k++) {
        int i = t * PER + k;
        if (i < NB) {
            int v = excl + loc[k];
            g_bstart[i] = v;
            g_bcur[i]   = v;
        }
    }
    if (t == 1023) g_bstart[NB] = ss[1023];
}

// k_place also zeroes acc1 (proven)
__global__ void k_place(const int* __restrict__ erow,
                        const int* __restrict__ ecol,
                        const float* __restrict__ eval) {
    int i = blockIdx.x * blockDim.x + threadIdx.x;
    if (i < N_ENT * D_EMB / 4)
        reinterpret_cast<float4*>(g_acc1)[i] = make_float4(0.f, 0.f, 0.f, 0.f);
    if (i >= NEDGE) return;
    int r   = i / E_EDGE;
    int col = __ldg(ecol + i);
    int b   = r * NTILE + (col >> 7);
    int pos = atomicAdd(&g_bcur[b], 1);
    g_recs[pos] = make_int2((__ldg(erow + i) << 7) | (col & 127),
                            __float_as_int(__ldg(eval + i)));
}

// ---------------------------------------------------------------------------
// FUSED layer — round-13 proven kernel; only the segment lookup changed
// (bucket index instead of per-key rowstart).
// ---------------------------------------------------------------------------
#define YW 68
#define SM_A 0                                  // A hi/lo: 2*128*AW = 9216 w
#define SM_B  (2 * 128 * AW)                    // 9216
#define BBUF  (2 * 32 * BW)                     // 4352 words per buffer
#define SM_TOT (SM_B + 2 * BBUF)                // 17920 words = 71680 B
// sY aliases words [0, 128*YW) = 8704 <= 9216

__global__ void __launch_bounds__(256, 2)
k_layer_fused(const float* __restrict__ rel_trans, int layer,
              int src_sel, int nrows) {
    extern __shared__ uint32_t sw[];
    uint32_t* sAh = sw + SM_A;
    uint32_t* sAl = sw + SM_A + 128 * AW;
    float*    sY  = reinterpret_cast<float*>(sw);   // aliases A region

    const int tid  = threadIdx.x;
    const int base = blockIdx.x * 128;
    const float* Wl   = rel_trans + (size_t)layer * R_REL * D_EMB * D_EMB;
    const float* Asrc = src_sel ? g_acc1 : g_emb;
    float*       aout = src_sel ? g_acc2 : g_acc1;

    // ---- stage A once ----
#pragma unroll
    for (int i = 0; i < 16; i++) {
        int p   = tid + i * 256;
        int row = p >> 5;
        int e2  = p & 31;
        float2 f = make_float2(0.f, 0.f);
        if (base + row < nrows)
            f = *reinterpret_cast<const float2*>(
                Asrc + (size_t)(base + row) * D_EMB + e2 * 2);
        if (src_sel) { f.x = fmaxf(f.x, 0.f); f.y = fmaxf(f.y, 0.f); }
        uint32_t h, l; split_pair(f, h, l);
        sAh[row * AW + e2] = h;
        sAl[row * AW + e2] = l;
    }

    // ---- stage B_0 into buffer 0 ----
    {
        uint32_t* bh = sw + SM_B;
        uint32_t* bl = bh + 32 * BW;
#pragma unroll
        for (int i = 0; i < 8; i++) {
            int p  = tid + i * 256;
            int d  = p >> 5;
            int e2 = p & 31;
            float2 f = *reinterpret_cast<const float2*>(Wl + d * 64 + e2 * 2);
            uint32_t h, l; split_pair(f, h, l);
            bh[e2 * BW + d] = h;
            bl[e2 * BW + d] = l;
        }
    }
    __syncthreads();

    const int warp = tid >> 5;
    const int lane = tid & 31;
    const int g = lane >> 2;
    const int t = lane & 3;
    const int wrow = warp * 16;
    const int d4 = tid & 15;
    const int eoff = tid >> 4;

    // ---- preload A fragments into registers ----
    uint32_t fah[4][4], fal[4][4];
#pragma unroll
    for (int ks = 0; ks < 4; ks++) {
        const int r0 = (wrow + g) * AW;
        const int r1 = (wrow + g + 8) * AW;
        const int eb = ks * 8 + t;
        fah[ks][0] = sAh[r0 + eb];     fah[ks][1] = sAh[r1 + eb];
        fah[ks][2] = sAh[r0 + eb + 4]; fah[ks][3] = sAh[r1 + eb + 4];
        fal[ks][0] = sAl[r0 + eb];     fal[ks][1] = sAl[r1 + eb];
        fal[ks][2] = sAl[r0 + eb + 4]; fal[ks][3] = sAl[r1 + eb + 4];
    }

    int p = 0;
    for (int r = 0; r < R_REL; r++) {
        const uint32_t* bh = sw + SM_B + p * BBUF;
        const uint32_t* bl = bh + 32 * BW;

        // ---- MMA (A from registers) ----
        float acc[8][4];
#pragma unroll
        for (int j = 0; j < 8; j++)
#pragma unroll
            for (int q = 0; q < 4; q++) acc[j][q] = 0.f;

#pragma unroll
        for (int ks = 0; ks < 4; ks++) {
            const int kb0 = (ks * 8 + t) * BW;
            const int kb1 = (ks * 8 + t + 4) * BW;
#pragma unroll
            for (int j = 0; j < 8; j++) {
                int n = j * 8 + g;
                uint32_t bh0 = bh[kb0 + n], bh1 = bh[kb1 + n];
                uint32_t bl0 = bl[kb0 + n], bl1 = bl[kb1 + n];
                MMA_BF16(acc[j], fah[ks], bh0, bh1);
                MMA_BF16(acc[j], fah[ks], bl0, bl1);
                MMA_BF16(acc[j], fal[ks], bh0, bh1);
            }
        }

        // ---- stage next B into other buffer ----
        if (r + 1 < R_REL) {
            const float* W = Wl + (size_t)(r + 1) * D_EMB * D_EMB;
            uint32_t* nbh = sw + SM_B + (p ^ 1) * BBUF;
            uint32_t* nbl = nbh + 32 * BW;
#pragma unroll
            for (int i = 0; i < 8; i++) {
                int q  = tid + i * 256;
                int d  = q >> 5;
                int e2 = q & 31;
                float2 f = *reinterpret_cast<const float2*>(W + d * 64 + e2 * 2);
                uint32_t h, l; split_pair(f, h, l);
                nbh[e2 * BW + d] = h;
                nbl[e2 * BW + d] = l;
            }
        }

        __syncthreads();   // scatter_{r-1} done with sY; frags loaded (r=0)

        // ---- write Y tile to SMEM (aliases A region) ----
#pragma unroll
        for (int j = 0; j < 8; j++) {
            int col = j * 8 + t * 2;
            *reinterpret_cast<float2*>(&sY[(wrow + g) * YW + col]) =
                make_float2(acc[j][0], acc[j][1]);
            *reinterpret_cast<float2*>(&sY[(wrow + g + 8) * YW + col]) =
                make_float2(acc[j][2], acc[j][3]);
        }

        __syncthreads();   // sY ready

        // ---- scatter this bucket's edges from SMEM ----
        {
            int b  = r * NTILE + blockIdx.x;
            int j0 = __ldg(&g_bstart[b]);
            int j1 = __ldg(&g_bstart[b + 1]);
            for (int j = j0 + eoff; j < j1; j += 16) {
                int2 rec = __ldg(&g_recs[j]);
                int drow = rec.x >> 7;
                int cl   = rec.x & 127;
                float v  = __int_as_float(rec.y);
                float4 q = *reinterpret_cast<const float4*>(&sY[cl * YW + d4 * 4]);
                float* dst = aout + (size_t)drow * D_EMB + d4 * 4;
                asm volatile("red.global.add.v4.f32 [%0], {%1,%2,%3,%4};"
                             :: "l"(dst), "f"(v * q.x), "f"(v * q.y),
                                "f"(v * q.z), "f"(v * q.w)
                             : "memory");
            }
        }

        p ^= 1;
    }

    // ---- layer-1 epilogue: zero this CTA's acc2 slice (proven) ----
    if (src_sel == 0) {
#pragma unroll
        for (int i = 0; i < 8; i++) {
            int q = tid + i * 256;
            int row = base + (q >> 4);
            if (row < nrows)
                reinterpret_cast<float4*>(g_acc2)[(size_t)row * 16 + (q & 15)] =
                    make_float4(0.f, 0.f, 0.f, 0.f);
        }
    }
}

// ---------------------------------------------------------------------------
// L2 normalize rows of relu(g_acc2)
// ---------------------------------------------------------------------------
__global__ void k_normalize(float* __restrict__ out) {
    int row  = blockIdx.x * 8 + (threadIdx.x >> 5);
    int lane = threadIdx.x & 31;
    if (row >= N_ENT) return;
    const float* e = g_acc2 + (size_t)row * D_EMB;
    float v0 = fmaxf(e[lane], 0.f), v1 = fmaxf(e[lane + 32], 0.f);
    float ss = v0 * v0 + v1 * v1;
#pragma unroll
    for (int o = 16; o > 0; o >>= 1) ss += __shfl_xor_sync(0xFFFFFFFFu, ss, o);
    float s = 1.0f / fmaxf(sqrtf(ss), 1e-12f);
    out[(size_t)row * D_EMB + lane]      = v0 * s;
    out[(size_t)row * D_EMB + lane + 32] = v1 * s;
}

// ---------------------------------------------------------------------------
extern "C" void kernel_launch(void* const* d_in, const int* in_sizes, int n_in,
                              void* d_out, int out_size) {
    const float* x         = (const float*)d_in[0];
    const float* ent_emb   = (const float*)d_in[1];
    const float* rel_trans = (const float*)d_in[2];
    const int*   erow      = (const int*)d_in[3];
    const int*   ecol      = (const int*)d_in[4];
    const float* eval      = (const float*)d_in[5];
    float* out             = (float*)d_out;

    const int tc_blocks   = NTILE;                            // 391
    const int edge_blocks = (NEDGE + 255) / 256;              // 6250
    const int row_warps   = (N_ENT + 7) / 8;

    const size_t smem_in = IN_SM_WORDS * sizeof(uint32_t);    // 54272
    const size_t smem_f  = SM_TOT * sizeof(uint32_t);         // 71680
    cudaFuncSetAttribute(k_input_hmma,
                         cudaFuncAttributeMaxDynamicSharedMemorySize, (int)smem_in);
    cudaFuncSetAttribute(k_layer_fused,
                         cudaFuncAttributeMaxDynamicSharedMemorySize, (int)smem_f);

    k_input_hmma<<<tc_blocks, 256, smem_in>>>(x, ent_emb, N_ENT);    // 0 (+zero cnt)
    k_hist<<<edge_blocks, 256>>>(ecol);                              // 1
    k_bscan<<<1, 1024>>>();                                          // 2
    k_place<<<edge_blocks, 256>>>(erow, ecol, eval);                 // 3 (+zero acc1)
    k_layer_fused<<<tc_blocks, 256, smem_f>>>(rel_trans, 0, 0, N_ENT); // 4
    k_layer_fused<<<tc_blocks, 256, smem_f>>>(rel_trans, 1, 1, N_ENT); // 5  <- ncu -s 5
    k_normalize<<<row_warps, 256>>>(out);                            // 6
}

// round 15
// speedup vs baseline: 1.2583x; 1.2583x over previous
#include <cuda_runtime.h>
#include <cstdint>

#define N_ENT 50000
#define R_REL 16
#define D_EMB 64
#define F_IN  128
#define E_EDGE 100000
#define NEDGE (R_REL * E_EDGE)          // 1.6M
#define NK (R_REL * N_ENT)              // 800000 keys (r*N + col)
#define NL 2

// ---------------- scratch (device globals; allocation-free rule) ------------
__device__ float g_emb[(size_t)N_ENT * D_EMB];                 // 12.8 MB
__device__ float g_acc1[(size_t)N_ENT * D_EMB];                // 12.8 MB (L2-hot)
__device__ float g_acc2[(size_t)N_ENT * D_EMB];                // 12.8 MB (L2-hot)
__device__ int   g_counts[NK];          // zero-invariant: place decrements back to 0
__device__ int   g_rowstart[NK + 1];    // chunk-local exclusive; final = + g_part
__device__ int2  g_recs[NEDGE];         // {(dest_row<<7)|col_local, val bits}
__device__ int   g_done;                // scan12 ticket (reset by last block)

#define SCHUNK 1024
#define NCH ((NK + SCHUNK - 1) / SCHUNK)                       // 782
__device__ int   g_part[NCH];

#define CVT_BF16X2(res, a, b) \
    asm("cvt.rn.satfinite.bf16x2.f32 %0, %1, %2;" : "=r"(res) : "f"(b), "f"(a))

__device__ __forceinline__ void split_pair(float2 f, uint32_t& h, uint32_t& l) {
    CVT_BF16X2(h, f.x, f.y);
    float h0 = __uint_as_float(h << 16);
    float h1 = __uint_as_float(h & 0xFFFF0000u);
    CVT_BF16X2(l, f.x - h0, f.y - h1);
}

#define MMA_BF16(c, a, b0, b1) \
    asm volatile("mma.sync.aligned.m16n8k16.row.col.f32.bf16.bf16.f32 " \
        "{%0,%1,%2,%3}, {%4,%5,%6,%7}, {%8,%9}, {%0,%1,%2,%3};" \
        : "+f"((c)[0]), "+f"((c)[1]), "+f"((c)[2]), "+f"((c)[3]) \
        : "r"((a)[0]), "r"((a)[1]), "r"((a)[2]), "r"((a)[3]), \
          "r"(b0), "r"(b1))

#define AW 36
#define BW 68

// final CSC offset for key i (chunk-local + chunk offset); i==NK holds total
__device__ __forceinline__ int seg_off(int i) {
    int v = __ldg(&g_rowstart[i]);
    if (i < NK) v += __ldg(&g_part[i >> 10]);
    return v;
}

// ---------------------------------------------------------------------------
// Input GEMM via HMMA (proven) + epilogue does CSC histogram (RED, no return)
// ---------------------------------------------------------------------------
#define IN_SM_AH 0
#define IN_SM_AL (128 * AW)
#define IN_SM_BH (2 * 128 * AW)
#define IN_SM_BL (2 * 128 * AW + 32 * BW)
#define IN_SM_WORDS (2 * 128 * AW + 2 * 32 * BW)   // 13568 words

__global__ void __launch_bounds__(256)
k_input_hmma(const float* __restrict__ x,
             const float* __restrict__ ent_emb,
             const int* __restrict__ ecol,
             int nrows) {
    extern __shared__ uint32_t sw[];
    uint32_t* sAh = sw + IN_SM_AH;
    uint32_t* sAl = sw + IN_SM_AL;
    uint32_t* sBh = sw + IN_SM_BH;
    uint32_t* sBl = sw + IN_SM_BL;

    const int tid  = threadIdx.x;
    const int base = blockIdx.x * 128;

    const int warp = tid >> 5;
    const int lane = tid & 31;
    const int g = lane >> 2;
    const int t = lane & 3;
    const int wrow = warp * 16;

    float acc[8][4];
#pragma unroll
    for (int j = 0; j < 8; j++)
#pragma unroll
        for (int q = 0; q < 4; q++) acc[j][q] = 0.f;

    for (int h = 0; h < 2; h++) {
        __syncthreads();
#pragma unroll
        for (int i = 0; i < 16; i++) {
            int p   = tid + i * 256;
            int row = p >> 5;
            int e2  = p & 31;
            float2 f = make_float2(0.f, 0.f);
            if (base + row < nrows)
                f = *reinterpret_cast<const float2*>(
                    x + (size_t)(base + row) * F_IN + h * 64 + e2 * 2);
            uint32_t hh, ll; split_pair(f, hh, ll);
            sAh[row * AW + e2] = hh;
            sAl[row * AW + e2] = ll;
        }
#pragma unroll
        for (int i = 0; i < 8; i++) {
            int p  = tid + i * 256;
            int d  = p >> 5;
            int e2 = p & 31;
            int k  = h * 64 + e2 * 2;
            float2 f = make_float2(ent_emb[(size_t)k * D_EMB + d],
                                   ent_emb[(size_t)(k + 1) * D_EMB + d]);
            uint32_t hh, ll; split_pair(f, hh, ll);
            sBh[e2 * BW + d] = hh;
            sBl[e2 * BW + d] = ll;
        }
        __syncthreads();

#pragma unroll
        for (int ks = 0; ks < 4; ks++) {
            const int r0 = (wrow + g) * AW;
            const int r1 = (wrow + g + 8) * AW;
            const int eb = ks * 8 + t;
            uint32_t ah[4], al[4];
            ah[0] = sAh[r0 + eb];     ah[1] = sAh[r1 + eb];
            ah[2] = sAh[r0 + eb + 4]; ah[3] = sAh[r1 + eb + 4];
            al[0] = sAl[r0 + eb];     al[1] = sAl[r1 + eb];
            al[2] = sAl[r0 + eb + 4]; al[3] = sAl[r1 + eb + 4];

            const int kb0 = (ks * 8 + t) * BW;
            const int kb1 = (ks * 8 + t + 4) * BW;
#pragma unroll
            for (int j = 0; j < 8; j++) {
                int n = j * 8 + g;
                uint32_t bh0 = sBh[kb0 + n], bh1 = sBh[kb1 + n];
                uint32_t bl0 = sBl[kb0 + n], bl1 = sBl[kb1 + n];
                MMA_BF16(acc[j], ah, bh0, bh1);
                MMA_BF16(acc[j], ah, bl0, bl1);
                MMA_BF16(acc[j], al, bh0, bh1);
            }
        }
    }

    {
        int row0 = base + wrow + g;
        int row1 = row0 + 8;
#pragma unroll
        for (int j = 0; j < 8; j++) {
            int col = j * 8 + t * 2;
            if (row0 < nrows)
                *reinterpret_cast<float2*>(g_emb + (size_t)row0 * D_EMB + col) =
                    make_float2(acc[j][0], acc[j][1]);
            if (row1 < nrows)
                *reinterpret_cast<float2*>(g_emb + (size_t)row1 * D_EMB + col) =
                    make_float2(acc[j][2], acc[j][3]);
        }
    }

    // epilogue: CSC histogram (counts start at 0: zero-init + place decrement
    // restores 0 every replay). atomicAdd result unused -> RED, fire-and-forget.
    {
        int gt = blockIdx.x * 256 + tid;
        int stride = gridDim.x * 256;
        for (int i = gt; i < NEDGE; i += stride) {
            int r = i / E_EDGE;
            atomicAdd(&g_counts[r * N_ENT + __ldg(ecol + i)], 1);
        }
    }
}

// ---------------------------------------------------------------------------
// scan over 800K keys: per-chunk exclusive + last-block chunk-offset scan
// (round-13 proven; resets g_done for the next replay)
// ---------------------------------------------------------------------------
__global__ void k_scan12() {
    __shared__ int ss[256];
    __shared__ int sdone;
    int b = blockIdx.x, t = threadIdx.x;
    int base = b * SCHUNK + t * 4;
    int4 c = make_int4(0, 0, 0, 0);
    if (base < NK) c = *reinterpret_cast<const int4*>(&g_counts[base]);
    int s = c.x + c.y + c.z + c.w;
    ss[t] = s;
    __syncthreads();
    for (int off = 1; off < 256; off <<= 1) {
        int v = (t >= off) ? ss[t - off] : 0;
        __syncthreads();
        ss[t] += v;
        __syncthreads();
    }
    int excl = ss[t] - s;
    if (t == 255) g_part[b] = ss[t];
    if (base < NK) {
        int r = excl;
        g_rowstart[base + 0] = r; r += c.x;
        g_rowstart[base + 1] = r; r += c.y;
        g_rowstart[base + 2] = r; r += c.z;
        g_rowstart[base + 3] = r;
    }

    if (t == 255) {
        __threadfence();
        int old = atomicAdd(&g_done, 1);
        sdone = (old == gridDim.x - 1) ? 1 : 0;
    }
    __syncthreads();
    if (sdone) {
        int v0 = 0, v1 = 0, v2 = 0, v3 = 0;
        int i0 = t * 4;
        if (i0 + 0 < NCH) v0 = g_part[i0 + 0];
        if (i0 + 1 < NCH) v1 = g_part[i0 + 1];
        if (i0 + 2 < NCH) v2 = g_part[i0 + 2];
        if (i0 + 3 < NCH) v3 = g_part[i0 + 3];
        int l0 = v0, l1 = l0 + v1, l2 = l1 + v2, l3 = l2 + v3;
        __syncthreads();
        ss[t] = l3;
        __syncthreads();
        for (int off = 1; off < 256; off <<= 1) {
            int v = (t >= off) ? ss[t - off] : 0;
            __syncthreads();
            ss[t] += v;
            __syncthreads();
        }
        int exclT = ss[t] - l3;
        if (i0 + 0 < NCH) g_part[i0 + 0] = exclT;
        if (i0 + 1 < NCH) g_part[i0 + 1] = exclT + l0;
        if (i0 + 2 < NCH) g_part[i0 + 2] = exclT + l1;
        if (i0 + 3 < NCH) g_part[i0 + 3] = exclT + l2;
        if (t == 255) g_rowstart[NK] = ss[255];
        __syncthreads();
        if (t == 0) g_done = 0;          // reset ticket for next replay
    }
}

// ---------------------------------------------------------------------------
// place (+ zero acc1): slot = final_offset(key) + (--count). Decrement returns
// counts to 0, preserving the zero-invariant for the next replay.
// ---------------------------------------------------------------------------
__global__ void k_place(const int* __restrict__ erow,
                        const int* __restrict__ ecol,
                        const float* __restrict__ eval) {
    int i = blockIdx.x * blockDim.x + threadIdx.x;
    if (i < N_ENT * D_EMB / 4)
        reinterpret_cast<float4*>(g_acc1)[i] = make_float4(0.f, 0.f, 0.f, 0.f);
    if (i >= NEDGE) return;
    int r   = i / E_EDGE;
    int col = __ldg(ecol + i);
    int key = r * N_ENT + col;
    int pos = seg_off(key) + atomicAdd(&g_counts[key], -1) - 1;
    g_recs[pos] = make_int2((__ldg(erow + i) << 7) | (col & 127),
                            __float_as_int(__ldg(eval + i)));
}

// ---------------------------------------------------------------------------
// FUSED layer — round-13 proven kernel; segment lookups use seg_off()
// ---------------------------------------------------------------------------
#define YW 68
#define SM_A 0                                  // A hi/lo: 2*128*AW = 9216 w
#define SM_B  (2 * 128 * AW)                    // 9216
#define BBUF  (2 * 32 * BW)                     // 4352 words per buffer
#define SM_TOT (SM_B + 2 * BBUF)                // 17920 words = 71680 B
// sY aliases words [0, 128*YW) = 8704 <= 9216

__global__ void __launch_bounds__(256, 2)
k_layer_fused(const float* __restrict__ rel_trans, int layer,
              int src_sel, int nrows) {
    extern __shared__ uint32_t sw[];
    uint32_t* sAh = sw + SM_A;
    uint32_t* sAl = sw + SM_A + 128 * AW;
    float*    sY  = reinterpret_cast<float*>(sw);   // aliases A region

    const int tid  = threadIdx.x;
    const int base = blockIdx.x * 128;
    const float* Wl   = rel_trans + (size_t)layer * R_REL * D_EMB * D_EMB;
    const float* Asrc = src_sel ? g_acc1 : g_emb;
    float*       aout = src_sel ? g_acc2 : g_acc1;

    // ---- stage A once ----
#pragma unroll
    for (int i = 0; i < 16; i++) {
        int p   = tid + i * 256;
        int row = p >> 5;
        int e2  = p & 31;
        float2 f = make_float2(0.f, 0.f);
        if (base + row < nrows)
            f = *reinterpret_cast<const float2*>(
                Asrc + (size_t)(base + row) * D_EMB + e2 * 2);
        if (src_sel) { f.x = fmaxf(f.x, 0.f); f.y = fmaxf(f.y, 0.f); }
        uint32_t h, l; split_pair(f, h, l);
        sAh[row * AW + e2] = h;
        sAl[row * AW + e2] = l;
    }

    // ---- stage B_0 into buffer 0 ----
    {
        uint32_t* bh = sw + SM_B;
        uint32_t* bl = bh + 32 * BW;
#pragma unroll
        for (int i = 0; i < 8; i++) {
            int p  = tid + i * 256;
            int d  = p >> 5;
            int e2 = p & 31;
            float2 f = *reinterpret_cast<const float2*>(Wl + d * 64 + e2 * 2);
            uint32_t h, l; split_pair(f, h, l);
            bh[e2 * BW + d] = h;
            bl[e2 * BW + d] = l;
        }
    }
    __syncthreads();

    const int warp = tid >> 5;
    const int lane = tid & 31;
    const int g = lane >> 2;
    const int t = lane & 3;
    const int wrow = warp * 16;
    const int d4 = tid & 15;
    const int eoff = tid >> 4;
    const int tile_hi = (base + 128 < nrows) ? base + 128 : nrows;

    // ---- preload A fragments into registers ----
    uint32_t fah[4][4], fal[4][4];
#pragma unroll
    for (int ks = 0; ks < 4; ks++) {
        const int r0 = (wrow + g) * AW;
        const int r1 = (wrow + g + 8) * AW;
        const int eb = ks * 8 + t;
        fah[ks][0] = sAh[r0 + eb];     fah[ks][1] = sAh[r1 + eb];
        fah[ks][2] = sAh[r0 + eb + 4]; fah[ks][3] = sAh[r1 + eb + 4];
        fal[ks][0] = sAl[r0 + eb];     fal[ks][1] = sAl[r1 + eb];
        fal[ks][2] = sAl[r0 + eb + 4]; fal[ks][3] = sAl[r1 + eb + 4];
    }

    int p = 0;
    for (int r = 0; r < R_REL; r++) {
        const uint32_t* bh = sw + SM_B + p * BBUF;
        const uint32_t* bl = bh + 32 * BW;

        // ---- MMA (A from registers) ----
        float acc[8][4];
#pragma unroll
        for (int j = 0; j < 8; j++)
#pragma unroll
            for (int q = 0; q < 4; q++) acc[j][q] = 0.f;

#pragma unroll
        for (int ks = 0; ks < 4; ks++) {
            const int kb0 = (ks * 8 + t) * BW;
            const int kb1 = (ks * 8 + t + 4) * BW;
#pragma unroll
            for (int j = 0; j < 8; j++) {
                int n = j * 8 + g;
                uint32_t bh0 = bh[kb0 + n], bh1 = bh[kb1 + n];
                uint32_t bl0 = bl[kb0 + n], bl1 = bl[kb1 + n];
                MMA_BF16(acc[j], fah[ks], bh0, bh1);
                MMA_BF16(acc[j], fah[ks], bl0, bl1);
                MMA_BF16(acc[j], fal[ks], bh0, bh1);
            }
        }

        // ---- stage next B into other buffer ----
        if (r + 1 < R_REL) {
            const float* W = Wl + (size_t)(r + 1) * D_EMB * D_EMB;
            uint32_t* nbh = sw + SM_B + (p ^ 1) * BBUF;
            uint32_t* nbl = nbh + 32 * BW;
#pragma unroll
            for (int i = 0; i < 8; i++) {
                int q  = tid + i * 256;
                int d  = q >> 5;
                int e2 = q & 31;
                float2 f = *reinterpret_cast<const float2*>(W + d * 64 + e2 * 2);
                uint32_t h, l; split_pair(f, h, l);
                nbh[e2 * BW + d] = h;
                nbl[e2 * BW + d] = l;
            }
        }

        __syncthreads();   // scatter_{r-1} done with sY; frags loaded (r=0)

        // ---- write Y tile to SMEM (aliases A region) ----
#pragma unroll
        for (int j = 0; j < 8; j++) {
            int col = j * 8 + t * 2;
            *reinterpret_cast<float2*>(&sY[(wrow + g) * YW + col]) =
                make_float2(acc[j][0], acc[j][1]);
            *reinterpret_cast<float2*>(&sY[(wrow + g + 8) * YW + col]) =
                make_float2(acc[j][2], acc[j][3]);
        }

        __syncthreads();   // sY ready

        // ---- scatter this (tile, r)'s edges from SMEM ----
        {
            int j0 = seg_off(r * N_ENT + base);
            int j1 = seg_off(r * N_ENT + tile_hi);
            for (int j = j0 + eoff; j < j1; j += 16) {
                int2 rec = __ldg(&g_recs[j]);
                int drow = rec.x >> 7;
                int cl   = rec.x & 127;
                float v  = __int_as_float(rec.y);
                float4 q = *reinterpret_cast<const float4*>(&sY[cl * YW + d4 * 4]);
                float* dst = aout + (size_t)drow * D_EMB + d4 * 4;
                asm volatile("red.global.add.v4.f32 [%0], {%1,%2,%3,%4};"
                             :: "l"(dst), "f"(v * q.x), "f"(v * q.y),
                                "f"(v * q.z), "f"(v * q.w)
                             : "memory");
            }
        }

        p ^= 1;
    }

    // ---- layer-1 epilogue: zero this CTA's acc2 slice (proven) ----
    if (src_sel == 0) {
#pragma unroll
        for (int i = 0; i < 8; i++) {
            int q = tid + i * 256;
            int row = base + (q >> 4);
            if (row < nrows)
                reinterpret_cast<float4*>(g_acc2)[(size_t)row * 16 + (q & 15)] =
                    make_float4(0.f, 0.f, 0.f, 0.f);
        }
    }
}

// ---------------------------------------------------------------------------
// L2 normalize rows of relu(g_acc2)
// ---------------------------------------------------------------------------
__global__ void k_normalize(float* __restrict__ out) {
    int row  = blockIdx.x * 8 + (threadIdx.x >> 5);
    int lane = threadIdx.x & 31;
    if (row >= N_ENT) return;
    const float* e = g_acc2 + (size_t)row * D_EMB;
    float v0 = fmaxf(e[lane], 0.f), v1 = fmaxf(e[lane + 32], 0.f);
    float ss = v0 * v0 + v1 * v1;
#pragma unroll
    for (int o = 16; o > 0; o >>= 1) ss += __shfl_xor_sync(0xFFFFFFFFu, ss, o);
    float s = 1.0f / fmaxf(sqrtf(ss), 1e-12f);
    out[(size_t)row * D_EMB + lane]      = v0 * s;
    out[(size_t)row * D_EMB + lane + 32] = v1 * s;
}

// ---------------------------------------------------------------------------
extern "C" void kernel_launch(void* const* d_in, const int* in_sizes, int n_in,
                              void* d_out, int out_size) {
    const float* x         = (const float*)d_in[0];
    const float* ent_emb   = (const float*)d_in[1];
    const float* rel_trans = (const float*)d_in[2];
    const int*   erow      = (const int*)d_in[3];
    const int*   ecol      = (const int*)d_in[4];
    const float* eval      = (const float*)d_in[5];
    float* out             = (float*)d_out;

    const int tc_blocks   = (N_ENT + 127) / 128;              // 391
    const int edge_blocks = (NEDGE + 255) / 256;              // 6250
    const int row_warps   = (N_ENT + 7) / 8;

    const size_t smem_in = IN_SM_WORDS * sizeof(uint32_t);    // 54272
    const size_t smem_f  = SM_TOT * sizeof(uint32_t);         // 71680
    cudaFuncSetAttribute(k_input_hmma,
                         cudaFuncAttributeMaxDynamicSharedMemorySize, (int)smem_in);
    cudaFuncSetAttribute(k_layer_fused,
                         cudaFuncAttributeMaxDynamicSharedMemorySize, (int)smem_f);

    // launch chain: fused layer 1 sits at idx 3 = the ncu capture slot
    k_input_hmma<<<tc_blocks, 256, smem_in>>>(x, ent_emb, ecol, N_ENT); // 0 (+hist)
    k_scan12<<<NCH, 256>>>();                                           // 1
    k_place<<<edge_blocks, 256>>>(erow, ecol, eval);                    // 2 (+zero acc1)
    k_layer_fused<<<tc_blocks, 256, smem_f>>>(rel_trans, 0, 0, N_ENT);  // 3 <- ncu
    k_layer_fused<<<tc_blocks, 256, smem_f>>>(rel_trans, 1, 1, N_ENT);  // 4
    k_normalize<<<row_warps, 256>>>(out);                               // 5
}

// round 16
// speedup vs baseline: 1.3289x; 1.0560x over previous
#include <cuda_runtime.h>
#include <cstdint>

#define N_ENT 50000
#define R_REL 16
#define D_EMB 64
#define F_IN  128
#define E_EDGE 100000
#define NEDGE (R_REL * E_EDGE)          // 1.6M
#define NK (R_REL * N_ENT)              // 800000 keys (r*N + col)
#define NTILE 782                        // ceil(N_ENT/64)
#define NL 2

// ---------------- scratch (device globals; allocation-free rule) ------------
__device__ float    g_emb[(size_t)N_ENT * D_EMB];              // 12.8 MB
__device__ float    g_acc1[(size_t)N_ENT * D_EMB];             // 12.8 MB (L2-hot)
__device__ float    g_acc2[(size_t)N_ENT * D_EMB];             // 12.8 MB (L2-hot)
__device__ int      g_counts[NK];       // zero-invariant (place decrements to 0)
__device__ int      g_rowstart[NK + 1]; // chunk-local exclusive; final = + g_part
__device__ int2     g_recs[NEDGE];      // {(dest_row<<6)|col_local, val bits}
__device__ int      g_done;
__device__ uint32_t g_wh[NL * R_REL * 32 * 64];   // pre-split W hi [lr][kpair][d]
__device__ uint32_t g_wl[NL * R_REL * 32 * 64];   // pre-split W lo

#define SCHUNK 1024
#define NCH ((NK + SCHUNK - 1) / SCHUNK)                       // 782
__device__ int   g_part[NCH];

#define CVT_BF16X2(res, a, b) \
    asm("cvt.rn.satfinite.bf16x2.f32 %0, %1, %2;" : "=r"(res) : "f"(b), "f"(a))

__device__ __forceinline__ void split_pair(float2 f, uint32_t& h, uint32_t& l) {
    CVT_BF16X2(h, f.x, f.y);
    float h0 = __uint_as_float(h << 16);
    float h1 = __uint_as_float(h & 0xFFFF0000u);
    CVT_BF16X2(l, f.x - h0, f.y - h1);
}

#define MMA_BF16(c, a, b0, b1) \
    asm volatile("mma.sync.aligned.m16n8k16.row.col.f32.bf16.bf16.f32 " \
        "{%0,%1,%2,%3}, {%4,%5,%6,%7}, {%8,%9}, {%0,%1,%2,%3};" \
        : "+f"((c)[0]), "+f"((c)[1]), "+f"((c)[2]), "+f"((c)[3]) \
        : "r"((a)[0]), "r"((a)[1]), "r"((a)[2]), "r"((a)[3]), \
          "r"(b0), "r"(b1))

#define AW 36
#define BW 68

// final CSC offset for key i; i==NK holds total
__device__ __forceinline__ int seg_off(int i) {
    int v = __ldg(&g_rowstart[i]);
    if (i < NK) v += __ldg(&g_part[i >> 10]);
    return v;
}

// ---------------------------------------------------------------------------
// Input GEMM via HMMA (proven) + epilogue: CSC histogram + weight pre-split
// ---------------------------------------------------------------------------
#define IN_SM_AH 0
#define IN_SM_AL (128 * AW)
#define IN_SM_BH (2 * 128 * AW)
#define IN_SM_BL (2 * 128 * AW + 32 * BW)
#define IN_SM_WORDS (2 * 128 * AW + 2 * 32 * BW)   // 13568 words

__global__ void __launch_bounds__(256)
k_input_hmma(const float* __restrict__ x,
             const float* __restrict__ ent_emb,
             const int* __restrict__ ecol,
             const float* __restrict__ rel_trans,
             int nrows) {
    extern __shared__ uint32_t sw[];
    uint32_t* sAh = sw + IN_SM_AH;
    uint32_t* sAl = sw + IN_SM_AL;
    uint32_t* sBh = sw + IN_SM_BH;
    uint32_t* sBl = sw + IN_SM_BL;

    const int tid  = threadIdx.x;
    const int base = blockIdx.x * 128;

    const int warp = tid >> 5;
    const int lane = tid & 31;
    const int g = lane >> 2;
    const int t = lane & 3;
    const int wrow = warp * 16;

    float acc[8][4];
#pragma unroll
    for (int j = 0; j < 8; j++)
#pragma unroll
        for (int q = 0; q < 4; q++) acc[j][q] = 0.f;

    for (int h = 0; h < 2; h++) {
        __syncthreads();
#pragma unroll
        for (int i = 0; i < 16; i++) {
            int p   = tid + i * 256;
            int row = p >> 5;
            int e2  = p & 31;
            float2 f = make_float2(0.f, 0.f);
            if (base + row < nrows)
                f = *reinterpret_cast<const float2*>(
                    x + (size_t)(base + row) * F_IN + h * 64 + e2 * 2);
            uint32_t hh, ll; split_pair(f, hh, ll);
            sAh[row * AW + e2] = hh;
            sAl[row * AW + e2] = ll;
        }
#pragma unroll
        for (int i = 0; i < 8; i++) {
            int p  = tid + i * 256;
            int d  = p >> 5;
            int e2 = p & 31;
            int k  = h * 64 + e2 * 2;
            float2 f = make_float2(ent_emb[(size_t)k * D_EMB + d],
                                   ent_emb[(size_t)(k + 1) * D_EMB + d]);
            uint32_t hh, ll; split_pair(f, hh, ll);
            sBh[e2 * BW + d] = hh;
            sBl[e2 * BW + d] = ll;
        }
        __syncthreads();

#pragma unroll
        for (int ks = 0; ks < 4; ks++) {
            const int r0 = (wrow + g) * AW;
            const int r1 = (wrow + g + 8) * AW;
            const int eb = ks * 8 + t;
            uint32_t ah[4], al[4];
            ah[0] = sAh[r0 + eb];     ah[1] = sAh[r1 + eb];
            ah[2] = sAh[r0 + eb + 4]; ah[3] = sAh[r1 + eb + 4];
            al[0] = sAl[r0 + eb];     al[1] = sAl[r1 + eb];
            al[2] = sAl[r0 + eb + 4]; al[3] = sAl[r1 + eb + 4];

            const int kb0 = (ks * 8 + t) * BW;
            const int kb1 = (ks * 8 + t + 4) * BW;
#pragma unroll
            for (int j = 0; j < 8; j++) {
                int n = j * 8 + g;
                uint32_t bh0 = sBh[kb0 + n], bh1 = sBh[kb1 + n];
                uint32_t bl0 = sBl[kb0 + n], bl1 = sBl[kb1 + n];
                MMA_BF16(acc[j], ah, bh0, bh1);
                MMA_BF16(acc[j], ah, bl0, bl1);
                MMA_BF16(acc[j], al, bh0, bh1);
            }
        }
    }

    {
        int row0 = base + wrow + g;
        int row1 = row0 + 8;
#pragma unroll
        for (int j = 0; j < 8; j++) {
            int col = j * 8 + t * 2;
            if (row0 < nrows)
                *reinterpret_cast<float2*>(g_emb + (size_t)row0 * D_EMB + col) =
                    make_float2(acc[j][0], acc[j][1]);
            if (row1 < nrows)
                *reinterpret_cast<float2*>(g_emb + (size_t)row1 * D_EMB + col) =
                    make_float2(acc[j][2], acc[j][3]);
        }
    }

    // epilogue 1: CSC histogram (RED; counts restored to 0 by place each replay)
    {
        int gt = blockIdx.x * 256 + tid;
        int stride = gridDim.x * 256;
        for (int i = gt; i < NEDGE; i += stride) {
            int r = i / E_EDGE;
            atomicAdd(&g_counts[r * N_ENT + __ldg(ecol + i)], 1);
        }
        // epilogue 2: pre-split all 32 weight matrices into g_wh/g_wl
        // layout: [lr][kpair e2][d] so fused-kernel B staging is a pure copy
        for (int i = gt; i < NL * R_REL * 32 * 64; i += stride) {
            int d  = i & 63;
            int e2 = (i >> 6) & 31;
            int lr = i >> 11;
            const float* W = rel_trans + (size_t)lr * D_EMB * D_EMB;
            float2 f = make_float2(W[d * 64 + e2 * 2], W[d * 64 + e2 * 2 + 1]);
            uint32_t h, l; split_pair(f, h, l);
            g_wh[i] = h;
            g_wl[i] = l;
        }
    }
}

// ---------------------------------------------------------------------------
// scan over 800K keys (round-15 proven; resets g_done)
// ---------------------------------------------------------------------------
__global__ void k_scan12() {
    __shared__ int ss[256];
    __shared__ int sdone;
    int b = blockIdx.x, t = threadIdx.x;
    int base = b * SCHUNK + t * 4;
    int4 c = make_int4(0, 0, 0, 0);
    if (base < NK) c = *reinterpret_cast<const int4*>(&g_counts[base]);
    int s = c.x + c.y + c.z + c.w;
    ss[t] = s;
    __syncthreads();
    for (int off = 1; off < 256; off <<= 1) {
        int v = (t >= off) ? ss[t - off] : 0;
        __syncthreads();
        ss[t] += v;
        __syncthreads();
    }
    int excl = ss[t] - s;
    if (t == 255) g_part[b] = ss[t];
    if (base < NK) {
        int r = excl;
        g_rowstart[base + 0] = r; r += c.x;
        g_rowstart[base + 1] = r; r += c.y;
        g_rowstart[base + 2] = r; r += c.z;
        g_rowstart[base + 3] = r;
    }

    if (t == 255) {
        __threadfence();
        int old = atomicAdd(&g_done, 1);
        sdone = (old == gridDim.x - 1) ? 1 : 0;
    }
    __syncthreads();
    if (sdone) {
        int v0 = 0, v1 = 0, v2 = 0, v3 = 0;
        int i0 = t * 4;
        if (i0 + 0 < NCH) v0 = g_part[i0 + 0];
        if (i0 + 1 < NCH) v1 = g_part[i0 + 1];
        if (i0 + 2 < NCH) v2 = g_part[i0 + 2];
        if (i0 + 3 < NCH) v3 = g_part[i0 + 3];
        int l0 = v0, l1 = l0 + v1, l2 = l1 + v2, l3 = l2 + v3;
        __syncthreads();
        ss[t] = l3;
        __syncthreads();
        for (int off = 1; off < 256; off <<= 1) {
            int v = (t >= off) ? ss[t - off] : 0;
            __syncthreads();
            ss[t] += v;
            __syncthreads();
        }
        int exclT = ss[t] - l3;
        if (i0 + 0 < NCH) g_part[i0 + 0] = exclT;
        if (i0 + 1 < NCH) g_part[i0 + 1] = exclT + l0;
        if (i0 + 2 < NCH) g_part[i0 + 2] = exclT + l1;
        if (i0 + 3 < NCH) g_part[i0 + 3] = exclT + l2;
        if (t == 255) g_rowstart[NK] = ss[255];
        __syncthreads();
        if (t == 0) g_done = 0;
    }
}

// ---------------------------------------------------------------------------
// place (+ zero acc1); 6-bit col_local for 64-row tiles
// ---------------------------------------------------------------------------
__global__ void k_place(const int* __restrict__ erow,
                        const int* __restrict__ ecol,
                        const float* __restrict__ eval) {
    int i = blockIdx.x * blockDim.x + threadIdx.x;
    if (i < N_ENT * D_EMB / 4)
        reinterpret_cast<float4*>(g_acc1)[i] = make_float4(0.f, 0.f, 0.f, 0.f);
    if (i >= NEDGE) return;
    int r   = i / E_EDGE;
    int col = __ldg(ecol + i);
    int key = r * N_ENT + col;
    int pos = seg_off(key) + atomicAdd(&g_counts[key], -1) - 1;
    g_recs[pos] = make_int2((__ldg(erow + i) << 6) | (col & 63),
                            __float_as_int(__ldg(eval + i)));
}

// ---------------------------------------------------------------------------
// FUSED layer — 64-row tiles (782 CTAs), 3 CTAs/SM target.
// Warp w: rows (w&3)*16 .. +15, cols (w>>2)*32 .. +31.  acc[4][4].
// B staging = pure copies of pre-split g_wh/g_wl.
// Structure (proven r10/13/15): MMA -> stage nextB -> sync -> write sY -> sync
//   -> scatter (REDG).  sY aliases A region.
// ---------------------------------------------------------------------------
#define YW 68
#define SM_A 0                                  // A hi/lo: 2*64*AW = 4608 w
#define SM_B  (2 * 64 * AW)                     // 4608
#define BBUF  (2 * 32 * BW)                     // 4352 words per buffer
#define SM_TOT (SM_B + 2 * BBUF)                // 13312 words = 53248 B
// sY aliases words [0, 64*YW) = 4352 <= 4608

__global__ void __launch_bounds__(256, 3)
k_layer_fused(int layer, int src_sel, int nrows) {
    extern __shared__ uint32_t sw[];
    uint32_t* sAh = sw + SM_A;
    uint32_t* sAl = sw + SM_A + 64 * AW;
    float*    sY  = reinterpret_cast<float*>(sw);   // aliases A region

    const int tid  = threadIdx.x;
    const int base = blockIdx.x * 64;
    const uint32_t* Wh = g_wh + (size_t)layer * R_REL * 2048;
    const uint32_t* Wlo = g_wl + (size_t)layer * R_REL * 2048;
    const float* Asrc = src_sel ? g_acc1 : g_emb;
    float*       aout = src_sel ? g_acc2 : g_acc1;

    // ---- stage A once: 64 rows x 32 epairs ----
#pragma unroll
    for (int i = 0; i < 8; i++) {
        int p   = tid + i * 256;
        int row = p >> 5;
        int e2  = p & 31;
        float2 f = make_float2(0.f, 0.f);
        if (base + row < nrows)
            f = *reinterpret_cast<const float2*>(
                Asrc + (size_t)(base + row) * D_EMB + e2 * 2);
        if (src_sel) { f.x = fmaxf(f.x, 0.f); f.y = fmaxf(f.y, 0.f); }
        uint32_t h, l; split_pair(f, h, l);
        sAh[row * AW + e2] = h;
        sAl[row * AW + e2] = l;
    }

    // ---- stage B_0 (copy) ----
    {
        uint32_t* bh = sw + SM_B;
        uint32_t* bl = bh + 32 * BW;
#pragma unroll
        for (int i = 0; i < 8; i++) {
            int p  = tid + i * 256;
            int e2 = p >> 6;
            int d  = p & 63;
            bh[e2 * BW + d] = Wh[p];
            bl[e2 * BW + d] = Wlo[p];
        }
    }
    __syncthreads();

    const int warp = tid >> 5;
    const int lane = tid & 31;
    const int g = lane >> 2;
    const int t = lane & 3;
    const int wrow = (warp & 3) * 16;
    const int cg   = (warp >> 2) * 32;
    const int d4 = tid & 15;
    const int eoff = tid >> 4;
    const int tile_hi = (base + 64 < nrows) ? base + 64 : nrows;

    // ---- preload A fragments (16 rows x K=64) ----
    uint32_t fah[4][4], fal[4][4];
#pragma unroll
    for (int ks = 0; ks < 4; ks++) {
        const int r0 = (wrow + g) * AW;
        const int r1 = (wrow + g + 8) * AW;
        const int eb = ks * 8 + t;
        fah[ks][0] = sAh[r0 + eb];     fah[ks][1] = sAh[r1 + eb];
        fah[ks][2] = sAh[r0 + eb + 4]; fah[ks][3] = sAh[r1 + eb + 4];
        fal[ks][0] = sAl[r0 + eb];     fal[ks][1] = sAl[r1 + eb];
        fal[ks][2] = sAl[r0 + eb + 4]; fal[ks][3] = sAl[r1 + eb + 4];
    }

    int p = 0;
    for (int r = 0; r < R_REL; r++) {
        const uint32_t* bh = sw + SM_B + p * BBUF;
        const uint32_t* bl = bh + 32 * BW;

        // ---- MMA: 16 rows x 32 cols ----
        float acc[4][4];
#pragma unroll
        for (int j = 0; j < 4; j++)
#pragma unroll
            for (int q = 0; q < 4; q++) acc[j][q] = 0.f;

#pragma unroll
        for (int ks = 0; ks < 4; ks++) {
            const int kb0 = (ks * 8 + t) * BW + cg;
            const int kb1 = (ks * 8 + t + 4) * BW + cg;
#pragma unroll
            for (int j = 0; j < 4; j++) {
                int n = j * 8 + g;
                uint32_t bh0 = bh[kb0 + n], bh1 = bh[kb1 + n];
                uint32_t bl0 = bl[kb0 + n], bl1 = bl[kb1 + n];
                MMA_BF16(acc[j], fah[ks], bh0, bh1);
                MMA_BF16(acc[j], fah[ks], bl0, bl1);
                MMA_BF16(acc[j], fal[ks], bh0, bh1);
            }
        }

        // ---- stage next B (copy) ----
        if (r + 1 < R_REL) {
            const uint32_t* nwh = Wh + (size_t)(r + 1) * 2048;
            const uint32_t* nwl = Wlo + (size_t)(r + 1) * 2048;
            uint32_t* nbh = sw + SM_B + (p ^ 1) * BBUF;
            uint32_t* nbl = nbh + 32 * BW;
#pragma unroll
            for (int i = 0; i < 8; i++) {
                int q  = tid + i * 256;
                int e2 = q >> 6;
                int d  = q & 63;
                nbh[e2 * BW + d] = nwh[q];
                nbl[e2 * BW + d] = nwl[q];
            }
        }

        __syncthreads();   // scatter_{r-1} done with sY; frags loaded (r=0)

        // ---- write Y tile to SMEM ----
#pragma unroll
        for (int j = 0; j < 4; j++) {
            int col = cg + j * 8 + t * 2;
            *reinterpret_cast<float2*>(&sY[(wrow + g) * YW + col]) =
                make_float2(acc[j][0], acc[j][1]);
            *reinterpret_cast<float2*>(&sY[(wrow + g + 8) * YW + col]) =
                make_float2(acc[j][2], acc[j][3]);
        }

        __syncthreads();   // sY ready

        // ---- scatter this (tile, r)'s edges from SMEM ----
        {
            int j0 = seg_off(r * N_ENT + base);
            int j1 = seg_off(r * N_ENT + tile_hi);
            for (int j = j0 + eoff; j < j1; j += 16) {
                int2 rec = __ldg(&g_recs[j]);
                int drow = rec.x >> 6;
                int cl   = rec.x & 63;
                float v  = __int_as_float(rec.y);
                float4 q = *reinterpret_cast<const float4*>(&sY[cl * YW + d4 * 4]);
                float* dst = aout + (size_t)drow * D_EMB + d4 * 4;
                asm volatile("red.global.add.v4.f32 [%0], {%1,%2,%3,%4};"
                             :: "l"(dst), "f"(v * q.x), "f"(v * q.y),
                                "f"(v * q.z), "f"(v * q.w)
                             : "memory");
            }
        }

        p ^= 1;
    }

    // ---- layer-1 epilogue: zero this CTA's acc2 slice ----
    if (src_sel == 0) {
#pragma unroll
        for (int i = 0; i < 4; i++) {
            int q = tid + i * 256;
            int row = base + (q >> 4);
            if (row < nrows)
                reinterpret_cast<float4*>(g_acc2)[(size_t)row * 16 + (q & 15)] =
                    make_float4(0.f, 0.f, 0.f, 0.f);
        }
    }
}

// ---------------------------------------------------------------------------
// L2 normalize rows of relu(g_acc2)
// ---------------------------------------------------------------------------
__global__ void k_normalize(float* __restrict__ out) {
    int row  = blockIdx.x * 8 + (threadIdx.x >> 5);
    int lane = threadIdx.x & 31;
    if (row >= N_ENT) return;
    const float* e = g_acc2 + (size_t)row * D_EMB;
    float v0 = fmaxf(e[lane], 0.f), v1 = fmaxf(e[lane + 32], 0.f);
    float ss = v0 * v0 + v1 * v1;
#pragma unroll
    for (int o = 16; o > 0; o >>= 1) ss += __shfl_xor_sync(0xFFFFFFFFu, ss, o);
    float s = 1.0f / fmaxf(sqrtf(ss), 1e-12f);
    out[(size_t)row * D_EMB + lane]      = v0 * s;
    out[(size_t)row * D_EMB + lane + 32] = v1 * s;
}

// ---------------------------------------------------------------------------
extern "C" void kernel_launch(void* const* d_in, const int* in_sizes, int n_in,
                              void* d_out, int out_size) {
    const float* x         = (const float*)d_in[0];
    const float* ent_emb   = (const float*)d_in[1];
    const float* rel_trans = (const float*)d_in[2];
    const int*   erow      = (const int*)d_in[3];
    const int*   ecol      = (const int*)d_in[4];
    const float* eval      = (const float*)d_in[5];
    float* out             = (float*)d_out;

    const int in_blocks   = (N_ENT + 127) / 128;              // 391
    const int edge_blocks = (NEDGE + 255) / 256;              // 6250
    const int row_warps   = (N_ENT + 7) / 8;

    const size_t smem_in = IN_SM_WORDS * sizeof(uint32_t);    // 54272
    const size_t smem_f  = SM_TOT * sizeof(uint32_t);         // 53248
    cudaFuncSetAttribute(k_input_hmma,
                         cudaFuncAttributeMaxDynamicSharedMemorySize, (int)smem_in);
    cudaFuncSetAttribute(k_layer_fused,
                         cudaFuncAttributeMaxDynamicSharedMemorySize, (int)smem_f);

    // launch chain: fused layer 1 at idx 3 = the ncu capture slot
    k_input_hmma<<<in_blocks, 256, smem_in>>>(x, ent_emb, ecol, rel_trans, N_ENT);
    k_scan12<<<NCH, 256>>>();
    k_place<<<edge_blocks, 256>>>(erow, ecol, eval);
    k_layer_fused<<<NTILE, 256, smem_f>>>(0, 0, N_ENT);   // idx 3 <- ncu
    k_layer_fused<<<NTILE, 256, smem_f>>>(1, 1, N_ENT);
    k_normalize<<<row_warps, 256>>>(out);
}